// round 3
// baseline (speedup 1.0000x reference)
#include <cuda_runtime.h>
#include <math.h>

// Problem constants (fixed by the dataset)
//  B=128, T=64, NA=10, NV=16, K=4, SD=512, H=256, E=32
#define T_TOK   64
#define N_AG    10
#define N_VAR   16
#define K_REL   4
#define SDIM    512
#define HDIM    256
#define EDIM    32

// shared memory layout (in floats)
//  sS   : [64][512]  states tile                        @ 0      (32768)
//  sH   : [64][256]  hidden buffer (reused A/B/C)       @ 32768  (16384)
//  sU1  : union 2048 @ 49152:
//         sQ   [64][10] qvals tile        @ +0    (640)
//         sW01 [64][10]                   @ +640  (640)
//         sHd  [256] h_delta              @ +1280 (256)
//         sW0  [64][4]                    @ +1536 (256)
//         sW0v [64][4]                    @ +1792 (256)
//         ---- reused from P5 as sHB2 [64][32] (2048)
//  sGQ  : [64][17]                        @ 51200 (1088)
//  sHID : [64][32]                        @ 52288 (2048)
//  sB1  : [64][32] (reused as sRED in P6) @ 54336 (2048)
//  sGB  : [64]                            @ 56384 (64)
//  sB01 : [64]                            @ 56448 (64)
//  sMisc: [16]  (g_delta at [0])          @ 56512 (16)
#define SMEM_FLOATS 56528
#define SMEM_BYTES  (SMEM_FLOATS * 4)

struct Params {
    const float* qvals;      // (128,64,10)
    const int*   cr;         // (128,64,4,16)
    const float* states;     // (128,64,512)
    const float* w00_l1_W;   // (528,256)
    const float* w00_l1_b;   // (256)
    const float* w00_l2_W;   // (256,4)
    const float* w00_l2_b;   // (4)
    const float* b00_W;      // (528,1)
    const float* b00_b;      // (1)
    const float* w01_W;      // (512,10)
    const float* w01_b;      // (10)
    const float* b01_W;      // (512,1)
    const float* b01_b;      // (1)
    const float* w1_l1_W;    // (512,256)
    const float* w1_l1_b;    // (256)
    const float* w1_l2_W;    // (256,544)
    const float* w1_l2_b;    // (544)
    const float* b1_W;       // (512,32)
    const float* b1_b;       // (32)
    const float* w2_l1_W;    // (512,256)
    const float* w2_l1_b;    // (256)
    const float* w2_l2_W;    // (256,32)
    const float* w2_l2_b;    // (32)
    const float* b2_l1_W;    // (512,32)
    const float* b2_l1_b;    // (32)
    const float* b2_l2_W;    // (32,1)
    const float* b2_l2_b;    // (1)
    float*       out;        // (128,64,1)
};

// Stage-1 GEMM: one thread owns one output column c of W (row-major [512][NC]),
// accumulates all 64 tokens in registers. Broadcast LDS.128 on states,
// coalesced LDG on W (lanes = consecutive c), software-prefetched one k-step.
template<int NC, bool RELU>
__device__ __forceinline__ void gemm_col(const float* __restrict__ sS,
                                         const float* __restrict__ W,
                                         int c, float bias,
                                         float* __restrict__ out, int outStride)
{
    float acc[64];
#pragma unroll
    for (int t = 0; t < 64; ++t) acc[t] = 0.f;

    const float* wp = W + c;
    float w0 = wp[0 * NC], w1 = wp[1 * NC], w2 = wp[2 * NC], w3 = wp[3 * NC];
#pragma unroll 1
    for (int k = 0; k < 512; k += 4) {
        const int kn = (k + 4 < 512) ? (k + 4) : 0;   // last prefetch is dummy (row 0, safe)
        const float n0 = wp[(kn + 0) * NC];
        const float n1 = wp[(kn + 1) * NC];
        const float n2 = wp[(kn + 2) * NC];
        const float n3 = wp[(kn + 3) * NC];
#pragma unroll
        for (int t = 0; t < 64; ++t) {
            const float4 s = *reinterpret_cast<const float4*>(sS + t * SDIM + k);
            float a = acc[t];
            a = fmaf(s.x, w0, a);
            a = fmaf(s.y, w1, a);
            a = fmaf(s.z, w2, a);
            a = fmaf(s.w, w3, a);
            acc[t] = a;
        }
        w0 = n0; w1 = n1; w2 = n2; w3 = n3;
    }
#pragma unroll
    for (int t = 0; t < 64; ++t) {
        float v = acc[t] + bias;
        if (RELU) v = fmaxf(v, 0.f);
        out[t * outStride] = v;
    }
}

// small per-item dot of state row against column c of row-major [512][NC] matrix
__device__ __forceinline__ float dot512(const float* __restrict__ sSt,
                                        const float* __restrict__ W,
                                        int NC, int c)
{
    float acc = 0.f;
#pragma unroll 4
    for (int k = 0; k < 512; k += 4) {
        const float4 s = *reinterpret_cast<const float4*>(sSt + k);
        acc = fmaf(s.x, W[(k + 0) * NC + c], acc);
        acc = fmaf(s.y, W[(k + 1) * NC + c], acc);
        acc = fmaf(s.z, W[(k + 2) * NC + c], acc);
        acc = fmaf(s.w, W[(k + 3) * NC + c], acc);
    }
    return acc;
}

extern __shared__ float smem[];

__global__ void __launch_bounds__(256, 1)
causal_mixer_kernel(Params p)
{
    const int tid = threadIdx.x;
    const int b   = blockIdx.x;          // one block == one batch index (64 tokens)

    float* sS    = smem;                 // 32768
    float* sH    = smem + 32768;         // 16384
    float* sU1   = smem + 49152;         // 2048 union
    float* sQ    = sU1;                  // 640
    float* sW01  = sU1 + 640;            // 640
    float* sHd   = sU1 + 1280;           // 256
    float* sW0   = sU1 + 1536;           // 256
    float* sW0v  = sU1 + 1792;           // 256
    float* sHB2  = sU1;                  // alias (valid from P5)
    float* sGQ   = smem + 51200;         // 1088
    float* sHID  = smem + 52288;         // 2048
    float* sB1   = smem + 54336;         // 2048
    float* sRED  = sB1;                  // alias (valid from P6)
    float* sGB   = smem + 56384;         // 64
    float* sB01  = smem + 56448;         // 64
    float* sMisc = smem + 56512;         // [0] = g_delta

    // ---------------- P0: load states + qvals tiles, h_delta / g_delta ----------------
    {
        const float4* src = reinterpret_cast<const float4*>(p.states + (size_t)b * T_TOK * SDIM);
        float4* dst = reinterpret_cast<float4*>(sS);
#pragma unroll
        for (int i = tid; i < T_TOK * SDIM / 4; i += 256) dst[i] = src[i];

        const float* qsrc = p.qvals + (size_t)b * T_TOK * N_AG;
        for (int i = tid; i < T_TOK * N_AG; i += 256) sQ[i] = qsrc[i];

        // h_delta[c] = sum of the one-hot rows (512..527) of w00_l1_W
        float hd = 0.f;
#pragma unroll
        for (int r = 0; r < N_VAR; ++r) hd += p.w00_l1_W[(SDIM + r) * HDIM + tid];
        sHd[tid] = hd;

        if (tid == 0) {
            float gd = 0.f;
#pragma unroll
            for (int r = 0; r < N_VAR; ++r) gd += p.b00_W[SDIM + r];
            sMisc[0] = gd;
        }
    }
    __syncthreads();

    // ---------------- P1: small stage-1 columns + A1 (w00_l1 pre-activation) ----------------
    {
        // 44 small columns x 64 tokens = 2816 items, 11 per thread.
        // Branch-free inner dot: branches only select per-lane operands.
#pragma unroll 1
        for (int r = 0; r < 11; ++r) {
            const int i = tid + r * 256;
            const int t = i / 44;
            const int j = i % 44;
            const float* sSt = sS + t * SDIM;

            const float* W; int NC, c; float bias; float* outp;
            if (j == 0)       { W = p.b00_W; NC = 1;  c = 0;      bias = p.b00_b[0];      outp = &sGB[t]; }
            else if (j == 1)  { W = p.b01_W; NC = 1;  c = 0;      bias = p.b01_b[0];      outp = &sB01[t]; }
            else if (j < 12)  { W = p.w01_W; NC = 10; c = j - 2;  bias = p.w01_b[c];      outp = &sW01[t * N_AG + c]; }
            else              { W = p.b1_W;  NC = 32; c = j - 12; bias = p.b1_b[c];       outp = &sB1[t * EDIM + c]; }

            *outp = dot512(sSt, W, NC, c) + bias;
        }
        // A1: h00 pre-activation (relu deferred; delta-variant needs pre-act)
        gemm_col<HDIM, false>(sS, p.w00_l1_W, tid, p.w00_l1_b[tid], sH + tid, HDIM);
    }
    __syncthreads();

    // ---------------- P2: A2 — per-token w0 (base + onehot variant) ----------------
    {
        const int t  = tid >> 2;
        const int k4 = tid & 3;
        float a = 0.f, av = 0.f;
#pragma unroll 4
        for (int c = 0; c < HDIM; ++c) {
            const float h  = sH[t * HDIM + c];
            const float w  = p.w00_l2_W[c * K_REL + k4];
            a  = fmaf(fmaxf(h, 0.f), w, a);
            av = fmaf(fmaxf(h + sHd[c], 0.f), w, av);
        }
        const float bias = p.w00_l2_b[k4];
        sW0 [t * K_REL + k4] = a  + bias;
        sW0v[t * K_REL + k4] = av + bias;
    }
    __syncthreads();

    // ---------------- P3: group + other -> gq ; then B1 (w1_l1, relu) ----------------
    {
        const float gdelta = sMisc[0];
#pragma unroll 1
        for (int r = 0; r < 4; ++r) {
            const int i = tid + r * 256;      // 1024 items = 64 tokens x 16 vars
            const int t = i >> 4;
            const int v = i & 15;
            const bool var = (v == b);
            const float* w0p = var ? (sW0v + t * K_REL) : (sW0 + t * K_REL);
            float g = sGB[t] + (var ? gdelta : 0.f);
            const int* crp = p.cr + (((size_t)b * T_TOK + t) * K_REL) * N_VAR + v;
#pragma unroll
            for (int k = 0; k < K_REL; ++k) {
                const int a = crp[k * N_VAR];
                g = fmaf(sQ[t * N_AG + a], fabsf(w0p[k]), g);
            }
            sGQ[t * 17 + v] = g;
        }
        if (tid < T_TOK) {
            const int t = tid;
            float o = sB01[t];
#pragma unroll
            for (int a = 0; a < N_AG; ++a)
                o = fmaf(sQ[t * N_AG + a], sW01[t * N_AG + a], o);
            sGQ[t * 17 + 16] = o;
        }
        // B1: h1 = relu(states @ w1_l1 + b) into sH
        gemm_col<HDIM, true>(sS, p.w1_l1_W, tid, p.w1_l1_b[tid], sH + tid, HDIM);
    }
    __syncthreads();

    // ---------------- P4: big stage-2 — w1 (256x544) fused with gq-mix + b1 + elu ----------------
    {
        const int e  = tid & 31;
        const int tg = tid >> 5;       // warp handles tokens tg*8 .. tg*8+7
        float hid[8];
#pragma unroll
        for (int j = 0; j < 8; ++j) hid[j] = sB1[(tg * 8 + j) * EDIM + e];

#pragma unroll 1
        for (int v = 0; v < N_VAR + 1; ++v) {
            float wa[8];
#pragma unroll
            for (int j = 0; j < 8; ++j) wa[j] = 0.f;

            const float* wp = p.w1_l2_W + v * EDIM + e;   // stride 544 over c
            float w0c = wp[0 * 544], w1c = wp[1 * 544], w2c = wp[2 * 544], w3c = wp[3 * 544];
#pragma unroll 1
            for (int c = 0; c < HDIM; c += 4) {
                const int cn = (c + 4 < HDIM) ? c + 4 : 0;
                const float n0 = wp[(cn + 0) * 544];
                const float n1 = wp[(cn + 1) * 544];
                const float n2 = wp[(cn + 2) * 544];
                const float n3 = wp[(cn + 3) * 544];
#pragma unroll
                for (int j = 0; j < 8; ++j) {
                    const float4 h = *reinterpret_cast<const float4*>(sH + (tg * 8 + j) * HDIM + c);
                    float a = wa[j];
                    a = fmaf(h.x, w0c, a);
                    a = fmaf(h.y, w1c, a);
                    a = fmaf(h.z, w2c, a);
                    a = fmaf(h.w, w3c, a);
                    wa[j] = a;
                }
                w0c = n0; w1c = n1; w2c = n2; w3c = n3;
            }
            const float bias = p.w1_l2_b[v * EDIM + e];
#pragma unroll
            for (int j = 0; j < 8; ++j) {
                const float wv = fabsf(wa[j] + bias);
                hid[j] = fmaf(sGQ[(tg * 8 + j) * 17 + v], wv, hid[j]);
            }
        }
#pragma unroll
        for (int j = 0; j < 8; ++j) {
            const float x = hid[j];
            sHID[(tg * 8 + j) * EDIM + e] = (x > 0.f) ? x : expm1f(x);
        }
    }
    __syncthreads();

    // ---------------- P5: C1 (w2_l1, relu) + b2 chain smalls ----------------
    {
        gemm_col<HDIM, true>(sS, p.w2_l1_W, tid, p.w2_l1_b[tid], sH + tid, HDIM);
        // b2: relu(states @ b2_l1 + b) * b2_l2_W[e]  (pre-multiplied, summed in P7)
#pragma unroll 1
        for (int r = 0; r < 8; ++r) {
            const int i = tid + r * 256;      // 2048 items
            const int t = i >> 5;
            const int e = i & 31;
            const float v = fmaxf(dot512(sS + t * SDIM, p.b2_l1_W, EDIM, e) + p.b2_l1_b[e], 0.f);
            sHB2[t * EDIM + e] = v * p.b2_l2_W[e];
        }
    }
    __syncthreads();

    // ---------------- P6: w2 (256x32) + hidden*w2 products ----------------
    {
        const int e  = tid & 31;
        const int tg = tid >> 5;
        float acc[8];
#pragma unroll
        for (int j = 0; j < 8; ++j) acc[j] = 0.f;

        const float* wp = p.w2_l2_W + e;
        float w0c = wp[0 * EDIM], w1c = wp[1 * EDIM], w2c = wp[2 * EDIM], w3c = wp[3 * EDIM];
#pragma unroll 1
        for (int c = 0; c < HDIM; c += 4) {
            const int cn = (c + 4 < HDIM) ? c + 4 : 0;
            const float n0 = wp[(cn + 0) * EDIM];
            const float n1 = wp[(cn + 1) * EDIM];
            const float n2 = wp[(cn + 2) * EDIM];
            const float n3 = wp[(cn + 3) * EDIM];
#pragma unroll
            for (int j = 0; j < 8; ++j) {
                const float4 h = *reinterpret_cast<const float4*>(sH + (tg * 8 + j) * HDIM + c);
                float a = acc[j];
                a = fmaf(h.x, w0c, a);
                a = fmaf(h.y, w1c, a);
                a = fmaf(h.z, w2c, a);
                a = fmaf(h.w, w3c, a);
                acc[j] = a;
            }
            w0c = n0; w1c = n1; w2c = n2; w3c = n3;
        }
        const float bias = p.w2_l2_b[e];
#pragma unroll
        for (int j = 0; j < 8; ++j) {
            const int t = tg * 8 + j;
            const float w2v = fabsf(acc[j] + bias);
            sRED[t * EDIM + e] = sHID[t * EDIM + e] * w2v;
        }
    }
    __syncthreads();

    // ---------------- P7: final reduction ----------------
    if (tid < T_TOK) {
        const int t = tid;
        float s1 = 0.f, s2 = 0.f;
#pragma unroll
        for (int e = 0; e < EDIM; ++e) {
            s1 += sRED[t * EDIM + e];
            s2 += sHB2[t * EDIM + e];
        }
        p.out[(size_t)b * T_TOK + t] = s1 + s2 + p.b2_l2_b[0];
    }
}

extern "C" void kernel_launch(void* const* d_in, const int* in_sizes, int n_in,
                              void* d_out, int out_size)
{
    Params p;
    p.qvals    = (const float*)d_in[0];
    p.cr       = (const int*)  d_in[1];
    p.states   = (const float*)d_in[2];
    p.w00_l1_W = (const float*)d_in[3];
    p.w00_l1_b = (const float*)d_in[4];
    p.w00_l2_W = (const float*)d_in[5];
    p.w00_l2_b = (const float*)d_in[6];
    p.b00_W    = (const float*)d_in[7];
    p.b00_b    = (const float*)d_in[8];
    p.w01_W    = (const float*)d_in[9];
    p.w01_b    = (const float*)d_in[10];
    p.b01_W    = (const float*)d_in[11];
    p.b01_b    = (const float*)d_in[12];
    p.w1_l1_W  = (const float*)d_in[13];
    p.w1_l1_b  = (const float*)d_in[14];
    p.w1_l2_W  = (const float*)d_in[15];
    p.w1_l2_b  = (const float*)d_in[16];
    p.b1_W     = (const float*)d_in[17];
    p.b1_b     = (const float*)d_in[18];
    p.w2_l1_W  = (const float*)d_in[19];
    p.w2_l1_b  = (const float*)d_in[20];
    p.w2_l2_W  = (const float*)d_in[21];
    p.w2_l2_b  = (const float*)d_in[22];
    p.b2_l1_W  = (const float*)d_in[23];
    p.b2_l1_b  = (const float*)d_in[24];
    p.b2_l2_W  = (const float*)d_in[25];
    p.b2_l2_b  = (const float*)d_in[26];
    p.out      = (float*)d_out;

    const int Bn = in_sizes[2] / (T_TOK * SDIM);   // = 128

    cudaFuncSetAttribute(causal_mixer_kernel,
                         cudaFuncAttributeMaxDynamicSharedMemorySize, SMEM_BYTES);
    causal_mixer_kernel<<<Bn, 256, SMEM_BYTES>>>(p);
}

// round 8
// speedup vs baseline: 1.0991x; 1.0991x over previous
#include <cuda_runtime.h>
#include <math.h>

// Problem constants (fixed by the dataset)
//  B=128, T=64, NA=10, NV=16, K=4, SD=512, H=256, E=32
#define T_TOK   64
#define N_AG    10
#define N_VAR   16
#define K_REL   4
#define SDIM    512
#define HDIM    256
#define EDIM    32
#define NT      512

// shared memory layout (in floats)
#define SMEM_FLOATS 56528
#define SMEM_BYTES  (SMEM_FLOATS * 4)

typedef unsigned long long ull;

__device__ __forceinline__ ull fma2(ull a, ull b, ull c) {
    ull d;
    asm("fma.rn.f32x2 %0, %1, %2, %3;" : "=l"(d) : "l"(a), "l"(b), "l"(c));
    return d;
}
__device__ __forceinline__ ull pack2(float lo, float hi) {
    ull r;
    asm("mov.b64 %0, {%1, %2};" : "=l"(r) : "f"(lo), "f"(hi));
    return r;
}
__device__ __forceinline__ float hsum2(ull v) {
    float a, b;
    asm("mov.b64 {%0, %1}, %2;" : "=f"(a), "=f"(b) : "l"(v));
    return a + b;
}

struct Params {
    const float* qvals;      // (128,64,10)
    const int*   cr;         // (128,64,4,16)
    const float* states;     // (128,64,512)
    const float* w00_l1_W;   // (528,256)
    const float* w00_l1_b;   // (256)
    const float* w00_l2_W;   // (256,4)
    const float* w00_l2_b;   // (4)
    const float* b00_W;      // (528,1)
    const float* b00_b;      // (1)
    const float* w01_W;      // (512,10)
    const float* w01_b;      // (10)
    const float* b01_W;      // (512,1)
    const float* b01_b;      // (1)
    const float* w1_l1_W;    // (512,256)
    const float* w1_l1_b;    // (256)
    const float* w1_l2_W;    // (256,544)
    const float* w1_l2_b;    // (544)
    const float* b1_W;       // (512,32)
    const float* b1_b;       // (32)
    const float* w2_l1_W;    // (512,256)
    const float* w2_l1_b;    // (256)
    const float* w2_l2_W;    // (256,32)
    const float* w2_l2_b;    // (32)
    const float* b2_l1_W;    // (512,32)
    const float* b2_l1_b;    // (32)
    const float* b2_l2_W;    // (32,1)
    const float* b2_l2_b;    // (1)
    float*       out;        // (128,64,1)
};

// Stage-1 GEMM, f32x2 version: one thread owns output column c and 32 tokens
// (t0..t0+31). States read from smem as ulonglong2 (LDS.128, broadcast within
// warp), weights packed per k-step (alu pipe), FFMA2 on fma pipe.
template<int NC, bool RELU>
__device__ __forceinline__ void gemm_col2(const float* __restrict__ sS,
                                          const float* __restrict__ W,
                                          int c, float bias, int t0,
                                          float* __restrict__ out, int outStride)
{
    ull acc[32];
#pragma unroll
    for (int t = 0; t < 32; ++t) acc[t] = 0ull;

    const float* wp = W + c;
    ull w01 = pack2(wp[0 * NC], wp[1 * NC]);
    ull w23 = pack2(wp[2 * NC], wp[3 * NC]);
#pragma unroll 1
    for (int k = 0; k < SDIM; k += 4) {
        const int kn = (k + 4 < SDIM) ? (k + 4) : 0;   // last prefetch dummy, safe
        const float n0 = wp[(kn + 0) * NC];
        const float n1 = wp[(kn + 1) * NC];
        const float n2 = wp[(kn + 2) * NC];
        const float n3 = wp[(kn + 3) * NC];
#pragma unroll
        for (int t = 0; t < 32; ++t) {
            const ulonglong2 sv =
                *reinterpret_cast<const ulonglong2*>(sS + (t0 + t) * SDIM + k);
            ull a = acc[t];
            a = fma2(sv.x, w01, a);
            a = fma2(sv.y, w23, a);
            acc[t] = a;
        }
        w01 = pack2(n0, n1);
        w23 = pack2(n2, n3);
    }
#pragma unroll
    for (int t = 0; t < 32; ++t) {
        float v = hsum2(acc[t]) + bias;
        if (RELU) v = fmaxf(v, 0.f);
        out[(t0 + t) * outStride] = v;
    }
}

// f32x2 dot of one state row vs column c of row-major [512][NC]
__device__ __forceinline__ float dot512_2(const float* __restrict__ sSt,
                                          const float* __restrict__ W,
                                          int NC, int c)
{
    ull acc = 0ull;
#pragma unroll 4
    for (int k = 0; k < SDIM; k += 4) {
        const ulonglong2 sv = *reinterpret_cast<const ulonglong2*>(sSt + k);
        const ull w01 = pack2(W[(k + 0) * NC + c], W[(k + 1) * NC + c]);
        const ull w23 = pack2(W[(k + 2) * NC + c], W[(k + 3) * NC + c]);
        acc = fma2(sv.x, w01, acc);
        acc = fma2(sv.y, w23, acc);
    }
    return hsum2(acc);
}

extern __shared__ float smem[];

__global__ void __launch_bounds__(NT, 1)
causal_mixer_kernel(Params p)
{
    const int tid = threadIdx.x;
    const int b   = blockIdx.x;          // one block == one batch index (64 tokens)

    float* sS    = smem;                 // [64][512]  32768
    float* sH    = smem + 32768;         // [64][256]  16384
    float* sU1   = smem + 49152;         // 2048 union
    float* sQ    = sU1;                  // [64][10]
    float* sW01  = sU1 + 640;            // [64][10]
    float* sHd   = sU1 + 1280;           // [256]
    float* sW0   = sU1 + 1536;           // [64][4]
    float* sW0v  = sU1 + 1792;           // [64][4]
    float* sHB2  = sU1;                  // alias [64][32] (valid from P5)
    float* sGQ   = smem + 51200;         // [64][17]
    float* sHID  = smem + 52288;         // [64][32]
    float* sB1   = smem + 54336;         // [64][32]
    float* sRED  = sB1;                  // alias (valid from P6)
    float* sGB   = smem + 56384;         // [64]
    float* sB01  = smem + 56448;         // [64]
    float* sMisc = smem + 56512;         // [0] = g_delta

    // ---------------- P0: load states + qvals, h_delta / g_delta ----------------
    // (R5 bug fixed: the old if/else ladder assumed >512 threads, leaving sHd
    //  uninitialized, g_delta unwritten, and sQ[512..639] unloaded.)
    {
        const float4* src = reinterpret_cast<const float4*>(p.states + (size_t)b * T_TOK * SDIM);
        float4* dst = reinterpret_cast<float4*>(sS);
#pragma unroll
        for (int i = tid; i < T_TOK * SDIM / 4; i += NT) dst[i] = src[i];

        const float* qsrc = p.qvals + (size_t)b * T_TOK * N_AG;
#pragma unroll
        for (int i = tid; i < T_TOK * N_AG; i += NT) sQ[i] = qsrc[i];

        if (tid < HDIM) {
            // h_delta[c] = sum of one-hot rows (512..527) of w00_l1_W
            float hd = 0.f;
#pragma unroll
            for (int r = 0; r < N_VAR; ++r) hd += p.w00_l1_W[(SDIM + r) * HDIM + tid];
            sHd[tid] = hd;
        }
        if (tid == 0) {
            float gd = 0.f;
#pragma unroll
            for (int r = 0; r < N_VAR; ++r) gd += p.b00_W[SDIM + r];
            sMisc[0] = gd;
        }
    }
    __syncthreads();

    // ---------------- P1: small stage-1 columns + A1 (w00_l1 pre-activation) ----------------
    {
        // 44 small columns x 64 tokens = 2816 items over 512 threads (6 rounds)
#pragma unroll 1
        for (int r = 0; r < 6; ++r) {
            const int i = tid + r * NT;
            if (i < 2816) {
                const int t = i / 44;
                const int j = i % 44;
                const float* sSt = sS + t * SDIM;

                const float* W; int NC, c; float bias; float* outp;
                if (j == 0)       { W = p.b00_W; NC = 1;  c = 0;      bias = p.b00_b[0]; outp = &sGB[t]; }
                else if (j == 1)  { W = p.b01_W; NC = 1;  c = 0;      bias = p.b01_b[0]; outp = &sB01[t]; }
                else if (j < 12)  { W = p.w01_W; NC = 10; c = j - 2;  bias = p.w01_b[c]; outp = &sW01[t * N_AG + c]; }
                else              { W = p.b1_W;  NC = 32; c = j - 12; bias = p.b1_b[c];  outp = &sB1[t * EDIM + c]; }

                *outp = dot512_2(sSt, W, NC, c) + bias;
            }
        }
        // A1: h00 pre-activation (relu deferred; delta-variant needs pre-act)
        const int c  = tid & 255;
        const int t0 = (tid >> 8) * 32;
        gemm_col2<HDIM, false>(sS, p.w00_l1_W, c, p.w00_l1_b[c], t0, sH + c, HDIM);
    }
    __syncthreads();

    // ---------------- P2: A2 — per-token w0 (base + onehot variant split over threads) ----------------
    {
        // 512 items = 64 tokens x 4 k x {base, variant}
        const int t    = tid >> 3;
        const int k4   = (tid >> 1) & 3;
        const int var  = tid & 1;
        float a = 0.f;
#pragma unroll 4
        for (int c = 0; c < HDIM; c += 4) {
            const float4 h4 = *reinterpret_cast<const float4*>(sH + t * HDIM + c);
            float h0 = h4.x, h1 = h4.y, h2 = h4.z, h3 = h4.w;
            if (var) { h0 += sHd[c]; h1 += sHd[c + 1]; h2 += sHd[c + 2]; h3 += sHd[c + 3]; }
            a = fmaf(fmaxf(h0, 0.f), p.w00_l2_W[(c + 0) * K_REL + k4], a);
            a = fmaf(fmaxf(h1, 0.f), p.w00_l2_W[(c + 1) * K_REL + k4], a);
            a = fmaf(fmaxf(h2, 0.f), p.w00_l2_W[(c + 2) * K_REL + k4], a);
            a = fmaf(fmaxf(h3, 0.f), p.w00_l2_W[(c + 3) * K_REL + k4], a);
        }
        a += p.w00_l2_b[k4];
        if (var) sW0v[t * K_REL + k4] = a;
        else     sW0 [t * K_REL + k4] = a;
    }
    __syncthreads();

    // ---------------- P3: group + other -> gq ; then B1 (w1_l1, relu) ----------------
    {
        const float gdelta = sMisc[0];
#pragma unroll 1
        for (int r = 0; r < 2; ++r) {
            const int i = tid + r * NT;       // 1024 items = 64 tokens x 16 vars
            const int t = i >> 4;
            const int v = i & 15;
            const bool var = (v == b);
            const float* w0p = var ? (sW0v + t * K_REL) : (sW0 + t * K_REL);
            float g = sGB[t] + (var ? gdelta : 0.f);
            const int* crp = p.cr + (((size_t)b * T_TOK + t) * K_REL) * N_VAR + v;
#pragma unroll
            for (int k = 0; k < K_REL; ++k) {
                const int a = crp[k * N_VAR];
                g = fmaf(sQ[t * N_AG + a], fabsf(w0p[k]), g);
            }
            sGQ[t * 17 + v] = g;
        }
        if (tid < T_TOK) {
            const int t = tid;
            float o = sB01[t];
#pragma unroll
            for (int a = 0; a < N_AG; ++a)
                o = fmaf(sQ[t * N_AG + a], sW01[t * N_AG + a], o);
            sGQ[t * 17 + 16] = o;
        }
        // B1: h1 = relu(states @ w1_l1 + b) into sH
        const int c  = tid & 255;
        const int t0 = (tid >> 8) * 32;
        gemm_col2<HDIM, true>(sS, p.w1_l1_W, c, p.w1_l1_b[c], t0, sH + c, HDIM);
    }
    __syncthreads();

    // ---------------- P4: big stage-2 — w1 (256x544) fused with gq-mix + b1 + elu ----------------
    {
        const int e  = tid & 31;
        const int tg = tid >> 5;       // 16 groups, each owns tokens tg*4 .. tg*4+3
        float hid[4];
#pragma unroll
        for (int j = 0; j < 4; ++j) hid[j] = sB1[(tg * 4 + j) * EDIM + e];

#pragma unroll 1
        for (int v = 0; v < N_VAR + 1; ++v) {
            ull wa[4];
#pragma unroll
            for (int j = 0; j < 4; ++j) wa[j] = 0ull;

            const float* wp = p.w1_l2_W + v * EDIM + e;   // stride 544 over c
            ull w01 = pack2(wp[0 * 544], wp[1 * 544]);
            ull w23 = pack2(wp[2 * 544], wp[3 * 544]);
#pragma unroll 1
            for (int c = 0; c < HDIM; c += 4) {
                const int cn = (c + 4 < HDIM) ? c + 4 : 0;
                const float n0 = wp[(cn + 0) * 544];
                const float n1 = wp[(cn + 1) * 544];
                const float n2 = wp[(cn + 2) * 544];
                const float n3 = wp[(cn + 3) * 544];
#pragma unroll
                for (int j = 0; j < 4; ++j) {
                    const ulonglong2 h =
                        *reinterpret_cast<const ulonglong2*>(sH + (tg * 4 + j) * HDIM + c);
                    ull a = wa[j];
                    a = fma2(h.x, w01, a);
                    a = fma2(h.y, w23, a);
                    wa[j] = a;
                }
                w01 = pack2(n0, n1);
                w23 = pack2(n2, n3);
            }
            const float bias = p.w1_l2_b[v * EDIM + e];
#pragma unroll
            for (int j = 0; j < 4; ++j) {
                const float wv = fabsf(hsum2(wa[j]) + bias);
                hid[j] = fmaf(sGQ[(tg * 4 + j) * 17 + v], wv, hid[j]);
            }
        }
#pragma unroll
        for (int j = 0; j < 4; ++j) {
            const float x = hid[j];
            sHID[(tg * 4 + j) * EDIM + e] = (x > 0.f) ? x : expm1f(x);
        }
    }
    __syncthreads();

    // ---------------- P5: C1 (w2_l1, relu) + b2 chain smalls ----------------
    {
        const int c  = tid & 255;
        const int t0 = (tid >> 8) * 32;
        gemm_col2<HDIM, true>(sS, p.w2_l1_W, c, p.w2_l1_b[c], t0, sH + c, HDIM);
        // b2: relu(states @ b2_l1 + b) * b2_l2_W[e]  (pre-multiplied, summed in P7)
#pragma unroll 1
        for (int r = 0; r < 4; ++r) {
            const int i = tid + r * NT;       // 2048 items
            const int t = i >> 5;
            const int e = i & 31;
            const float v = fmaxf(dot512_2(sS + t * SDIM, p.b2_l1_W, EDIM, e) + p.b2_l1_b[e], 0.f);
            sHB2[t * EDIM + e] = v * p.b2_l2_W[e];
        }
    }
    __syncthreads();

    // ---------------- P6: w2 (256x32) + hidden*w2 products ----------------
    {
        const int e  = tid & 31;
        const int tg = tid >> 5;
        ull acc[4];
#pragma unroll
        for (int j = 0; j < 4; ++j) acc[j] = 0ull;

        const float* wp = p.w2_l2_W + e;
        ull w01 = pack2(wp[0 * EDIM], wp[1 * EDIM]);
        ull w23 = pack2(wp[2 * EDIM], wp[3 * EDIM]);
#pragma unroll 1
        for (int c = 0; c < HDIM; c += 4) {
            const int cn = (c + 4 < HDIM) ? c + 4 : 0;
            const float n0 = wp[(cn + 0) * EDIM];
            const float n1 = wp[(cn + 1) * EDIM];
            const float n2 = wp[(cn + 2) * EDIM];
            const float n3 = wp[(cn + 3) * EDIM];
#pragma unroll
            for (int j = 0; j < 4; ++j) {
                const ulonglong2 h =
                    *reinterpret_cast<const ulonglong2*>(sH + (tg * 4 + j) * HDIM + c);
                ull a = acc[j];
                a = fma2(h.x, w01, a);
                a = fma2(h.y, w23, a);
                acc[j] = a;
            }
            w01 = pack2(n0, n1);
            w23 = pack2(n2, n3);
        }
        const float bias = p.w2_l2_b[e];
#pragma unroll
        for (int j = 0; j < 4; ++j) {
            const int t = tg * 4 + j;
            const float w2v = fabsf(hsum2(acc[j]) + bias);
            sRED[t * EDIM + e] = sHID[t * EDIM + e] * w2v;
        }
    }
    __syncthreads();

    // ---------------- P7: final reduction ----------------
    if (tid < T_TOK) {
        const int t = tid;
        float s1 = 0.f, s2 = 0.f;
#pragma unroll
        for (int e = 0; e < EDIM; ++e) {
            s1 += sRED[t * EDIM + e];
            s2 += sHB2[t * EDIM + e];
        }
        p.out[(size_t)b * T_TOK + t] = s1 + s2 + p.b2_l2_b[0];
    }
}

extern "C" void kernel_launch(void* const* d_in, const int* in_sizes, int n_in,
                              void* d_out, int out_size)
{
    Params p;
    p.qvals    = (const float*)d_in[0];
    p.cr       = (const int*)  d_in[1];
    p.states   = (const float*)d_in[2];
    p.w00_l1_W = (const float*)d_in[3];
    p.w00_l1_b = (const float*)d_in[4];
    p.w00_l2_W = (const float*)d_in[5];
    p.w00_l2_b = (const float*)d_in[6];
    p.b00_W    = (const float*)d_in[7];
    p.b00_b    = (const float*)d_in[8];
    p.w01_W    = (const float*)d_in[9];
    p.w01_b    = (const float*)d_in[10];
    p.b01_W    = (const float*)d_in[11];
    p.b01_b    = (const float*)d_in[12];
    p.w1_l1_W  = (const float*)d_in[13];
    p.w1_l1_b  = (const float*)d_in[14];
    p.w1_l2_W  = (const float*)d_in[15];
    p.w1_l2_b  = (const float*)d_in[16];
    p.b1_W     = (const float*)d_in[17];
    p.b1_b     = (const float*)d_in[18];
    p.w2_l1_W  = (const float*)d_in[19];
    p.w2_l1_b  = (const float*)d_in[20];
    p.w2_l2_W  = (const float*)d_in[21];
    p.w2_l2_b  = (const float*)d_in[22];
    p.b2_l1_W  = (const float*)d_in[23];
    p.b2_l1_b  = (const float*)d_in[24];
    p.b2_l2_W  = (const float*)d_in[25];
    p.b2_l2_b  = (const float*)d_in[26];
    p.out      = (float*)d_out;

    const int Bn = in_sizes[2] / (T_TOK * SDIM);   // = 128

    cudaFuncSetAttribute(causal_mixer_kernel,
                         cudaFuncAttributeMaxDynamicSharedMemorySize, SMEM_BYTES);
    causal_mixer_kernel<<<Bn, NT, SMEM_BYTES>>>(p);
}

// round 9
// speedup vs baseline: 1.5062x; 1.3704x over previous
#include <cuda_runtime.h>
#include <math.h>

// Problem constants (fixed by the dataset)
//  B=128, T=64, NA=10, NV=16, K=4, SD=512, H=256, E=32
#define T_TOK   64
#define N_AG    10
#define N_VAR   16
#define K_REL   4
#define SDIM    512
#define HDIM    256
#define EDIM    32
#define NT      512

// shared memory layout (in floats)
#define SMEM_FLOATS 56528
#define SMEM_BYTES  (SMEM_FLOATS * 4)

typedef unsigned long long ull;

__device__ __forceinline__ ull fma2(ull a, ull b, ull c) {
    ull d;
    asm("fma.rn.f32x2 %0, %1, %2, %3;" : "=l"(d) : "l"(a), "l"(b), "l"(c));
    return d;
}
__device__ __forceinline__ ull pack2(float lo, float hi) {
    ull r;
    asm("mov.b64 %0, {%1, %2};" : "=l"(r) : "f"(lo), "f"(hi));
    return r;
}
__device__ __forceinline__ float hsum2(ull v) {
    float a, b;
    asm("mov.b64 {%0, %1}, %2;" : "=f"(a), "=f"(b) : "l"(v));
    return a + b;
}

struct Params {
    const float* qvals;      // (128,64,10)
    const int*   cr;         // (128,64,4,16)
    const float* states;     // (128,64,512)
    const float* w00_l1_W;   // (528,256)
    const float* w00_l1_b;   // (256)
    const float* w00_l2_W;   // (256,4)
    const float* w00_l2_b;   // (4)
    const float* b00_W;      // (528,1)
    const float* b00_b;      // (1)
    const float* w01_W;      // (512,10)
    const float* w01_b;      // (10)
    const float* b01_W;      // (512,1)
    const float* b01_b;      // (1)
    const float* w1_l1_W;    // (512,256)
    const float* w1_l1_b;    // (256)
    const float* w1_l2_W;    // (256,544)
    const float* w1_l2_b;    // (544)
    const float* b1_W;       // (512,32)
    const float* b1_b;       // (32)
    const float* w2_l1_W;    // (512,256)
    const float* w2_l1_b;    // (256)
    const float* w2_l2_W;    // (256,32)
    const float* w2_l2_b;    // (32)
    const float* b2_l1_W;    // (512,32)
    const float* b2_l1_b;    // (32)
    const float* b2_l2_W;    // (32,1)
    const float* b2_l2_b;    // (1)
    float*       out;        // (128,64,1)
};

// Stage-1 GEMM, column-PAIR version: one thread owns columns (c0, c0+1) and
// 16 tokens. One LDS.128 of states feeds FOUR FFMA2 (two per column), so
// FMA:LDS = 4:1 (was 2:1). Weights load as coalesced float2 per k-row.
template<int NC, bool RELU>
__device__ __forceinline__ void gemm_colpair(const float* __restrict__ sS,
                                             const float* __restrict__ W,
                                             int c0, float bias0, float bias1,
                                             int t0, float* __restrict__ out)
{
    ull a0[16], a1[16];
#pragma unroll
    for (int t = 0; t < 16; ++t) { a0[t] = 0ull; a1[t] = 0ull; }

    const float* wp = W + c0;        // c0 even; float2 covers cols c0, c0+1
    float2 r0 = *reinterpret_cast<const float2*>(wp + 0 * NC);
    float2 r1 = *reinterpret_cast<const float2*>(wp + 1 * NC);
    float2 r2 = *reinterpret_cast<const float2*>(wp + 2 * NC);
    float2 r3 = *reinterpret_cast<const float2*>(wp + 3 * NC);
#pragma unroll 1
    for (int k = 0; k < SDIM; k += 4) {
        const int kn = (k + 4 < SDIM) ? (k + 4) : 0;   // last prefetch dummy, safe
        const float2 n0 = *reinterpret_cast<const float2*>(wp + (kn + 0) * NC);
        const float2 n1 = *reinterpret_cast<const float2*>(wp + (kn + 1) * NC);
        const float2 n2 = *reinterpret_cast<const float2*>(wp + (kn + 2) * NC);
        const float2 n3 = *reinterpret_cast<const float2*>(wp + (kn + 3) * NC);

        const ull w01_0 = pack2(r0.x, r1.x), w23_0 = pack2(r2.x, r3.x);
        const ull w01_1 = pack2(r0.y, r1.y), w23_1 = pack2(r2.y, r3.y);
#pragma unroll
        for (int t = 0; t < 16; ++t) {
            const ulonglong2 sv =
                *reinterpret_cast<const ulonglong2*>(sS + (t0 + t) * SDIM + k);
            ull x0 = a0[t], x1 = a1[t];
            x0 = fma2(sv.x, w01_0, x0);
            x1 = fma2(sv.x, w01_1, x1);
            x0 = fma2(sv.y, w23_0, x0);
            x1 = fma2(sv.y, w23_1, x1);
            a0[t] = x0; a1[t] = x1;
        }
        r0 = n0; r1 = n1; r2 = n2; r3 = n3;
    }
#pragma unroll
    for (int t = 0; t < 16; ++t) {
        float v0 = hsum2(a0[t]) + bias0;
        float v1 = hsum2(a1[t]) + bias1;
        if (RELU) { v0 = fmaxf(v0, 0.f); v1 = fmaxf(v1, 0.f); }
        // c0 even -> 8B-aligned STS.64
        *reinterpret_cast<float2*>(out + (t0 + t) * NC + c0) = make_float2(v0, v1);
    }
}

// f32x2 dot of one state row vs column c of row-major [512][NC]
__device__ __forceinline__ float dot512_2(const float* __restrict__ sSt,
                                          const float* __restrict__ W,
                                          int NC, int c)
{
    ull acc = 0ull;
#pragma unroll 4
    for (int k = 0; k < SDIM; k += 4) {
        const ulonglong2 sv = *reinterpret_cast<const ulonglong2*>(sSt + k);
        const ull w01 = pack2(W[(k + 0) * NC + c], W[(k + 1) * NC + c]);
        const ull w23 = pack2(W[(k + 2) * NC + c], W[(k + 3) * NC + c]);
        acc = fma2(sv.x, w01, acc);
        acc = fma2(sv.y, w23, acc);
    }
    return hsum2(acc);
}

extern __shared__ float smem[];

__global__ void __launch_bounds__(NT, 1)
causal_mixer_kernel(Params p)
{
    const int tid = threadIdx.x;
    const int b   = blockIdx.x;          // one block == one batch index (64 tokens)

    float* sS    = smem;                 // [64][512]  32768
    float* sH    = smem + 32768;         // [64][256]  16384
    float* sU1   = smem + 49152;         // 2048 union
    float* sQ    = sU1;                  // [64][10]
    float* sW01  = sU1 + 640;            // [64][10]
    float* sHd   = sU1 + 1280;           // [256]
    float* sW0   = sU1 + 1536;           // [64][4]
    float* sW0v  = sU1 + 1792;           // [64][4]
    float* sHB2  = sU1;                  // alias [64][32] (valid from P5)
    float* sGQ   = smem + 51200;         // [64][17]
    float* sHID  = smem + 52288;         // [64][32]
    float* sB1   = smem + 54336;         // [64][32]
    float* sRED  = sB1;                  // alias (valid from P6)
    float* sGB   = smem + 56384;         // [64]
    float* sB01  = smem + 56448;         // [64]
    float* sMisc = smem + 56512;         // [0] = g_delta

    // per-thread gemm coordinates: 128 column-pairs x 4 token-groups of 16
    const int gc0 = (tid & 127) * 2;
    const int gt0 = (tid >> 7) * 16;

    // ---------------- P0: load states + qvals, h_delta / g_delta ----------------
    {
        const float4* src = reinterpret_cast<const float4*>(p.states + (size_t)b * T_TOK * SDIM);
        float4* dst = reinterpret_cast<float4*>(sS);
#pragma unroll
        for (int i = tid; i < T_TOK * SDIM / 4; i += NT) dst[i] = src[i];

        const float* qsrc = p.qvals + (size_t)b * T_TOK * N_AG;
#pragma unroll
        for (int i = tid; i < T_TOK * N_AG; i += NT) sQ[i] = qsrc[i];

        if (tid < HDIM) {
            // h_delta[c] = sum of one-hot rows (512..527) of w00_l1_W
            float hd = 0.f;
#pragma unroll
            for (int r = 0; r < N_VAR; ++r) hd += p.w00_l1_W[(SDIM + r) * HDIM + tid];
            sHd[tid] = hd;
        }
        if (tid == 0) {
            float gd = 0.f;
#pragma unroll
            for (int r = 0; r < N_VAR; ++r) gd += p.b00_W[SDIM + r];
            sMisc[0] = gd;
        }
    }
    __syncthreads();

    // ---------------- P1: small stage-1 columns + A1 (w00_l1 pre-activation) ----------------
    {
        // 44 small columns x 64 tokens = 2816 items over 512 threads (6 rounds)
#pragma unroll 1
        for (int r = 0; r < 6; ++r) {
            const int i = tid + r * NT;
            if (i < 2816) {
                const int t = i / 44;
                const int j = i % 44;
                const float* sSt = sS + t * SDIM;

                const float* W; int NC, c; float bias; float* outp;
                if (j == 0)       { W = p.b00_W; NC = 1;  c = 0;      bias = p.b00_b[0]; outp = &sGB[t]; }
                else if (j == 1)  { W = p.b01_W; NC = 1;  c = 0;      bias = p.b01_b[0]; outp = &sB01[t]; }
                else if (j < 12)  { W = p.w01_W; NC = 10; c = j - 2;  bias = p.w01_b[c]; outp = &sW01[t * N_AG + c]; }
                else              { W = p.b1_W;  NC = 32; c = j - 12; bias = p.b1_b[c];  outp = &sB1[t * EDIM + c]; }

                *outp = dot512_2(sSt, W, NC, c) + bias;
            }
        }
        // A1: h00 pre-activation (relu deferred; delta-variant needs pre-act)
        gemm_colpair<HDIM, false>(sS, p.w00_l1_W, gc0,
                                  p.w00_l1_b[gc0], p.w00_l1_b[gc0 + 1], gt0, sH);
    }
    __syncthreads();

    // ---------------- P2: A2 — per-token w0 (base + onehot variant split over threads) ----------------
    {
        // 512 items = 64 tokens x 4 k x {base, variant}
        const int t    = tid >> 3;
        const int k4   = (tid >> 1) & 3;
        const int var  = tid & 1;
        float a = 0.f;
#pragma unroll 4
        for (int c = 0; c < HDIM; c += 4) {
            const float4 h4 = *reinterpret_cast<const float4*>(sH + t * HDIM + c);
            float h0 = h4.x, h1 = h4.y, h2 = h4.z, h3 = h4.w;
            if (var) { h0 += sHd[c]; h1 += sHd[c + 1]; h2 += sHd[c + 2]; h3 += sHd[c + 3]; }
            a = fmaf(fmaxf(h0, 0.f), p.w00_l2_W[(c + 0) * K_REL + k4], a);
            a = fmaf(fmaxf(h1, 0.f), p.w00_l2_W[(c + 1) * K_REL + k4], a);
            a = fmaf(fmaxf(h2, 0.f), p.w00_l2_W[(c + 2) * K_REL + k4], a);
            a = fmaf(fmaxf(h3, 0.f), p.w00_l2_W[(c + 3) * K_REL + k4], a);
        }
        a += p.w00_l2_b[k4];
        if (var) sW0v[t * K_REL + k4] = a;
        else     sW0 [t * K_REL + k4] = a;
    }
    __syncthreads();

    // ---------------- P3: group + other -> gq ; then B1 (w1_l1, relu) ----------------
    {
        const float gdelta = sMisc[0];
#pragma unroll 1
        for (int r = 0; r < 2; ++r) {
            const int i = tid + r * NT;       // 1024 items = 64 tokens x 16 vars
            const int t = i >> 4;
            const int v = i & 15;
            const bool var = (v == b);
            const float* w0p = var ? (sW0v + t * K_REL) : (sW0 + t * K_REL);
            float g = sGB[t] + (var ? gdelta : 0.f);
            const int* crp = p.cr + (((size_t)b * T_TOK + t) * K_REL) * N_VAR + v;
#pragma unroll
            for (int k = 0; k < K_REL; ++k) {
                const int a = crp[k * N_VAR];
                g = fmaf(sQ[t * N_AG + a], fabsf(w0p[k]), g);
            }
            sGQ[t * 17 + v] = g;
        }
        if (tid < T_TOK) {
            const int t = tid;
            float o = sB01[t];
#pragma unroll
            for (int a = 0; a < N_AG; ++a)
                o = fmaf(sQ[t * N_AG + a], sW01[t * N_AG + a], o);
            sGQ[t * 17 + 16] = o;
        }
        // B1: h1 = relu(states @ w1_l1 + b) into sH
        gemm_colpair<HDIM, true>(sS, p.w1_l1_W, gc0,
                                 p.w1_l1_b[gc0], p.w1_l1_b[gc0 + 1], gt0, sH);
    }
    __syncthreads();

    // ---------------- P4: big stage-2 — w1 (256x544) fused with gq-mix + b1 + elu ----------------
    // v-columns processed in PAIRS: one LDS.128 of hidden feeds 4 FFMA2.
    {
        const int e  = tid & 31;
        const int tg = tid >> 5;       // 16 groups, each owns tokens tg*4 .. tg*4+3
        float hid[4];
#pragma unroll
        for (int j = 0; j < 4; ++j) hid[j] = sB1[(tg * 4 + j) * EDIM + e];

#pragma unroll 1
        for (int vp = 0; vp < 8; ++vp) {
            ull a0[4], a1[4];
#pragma unroll
            for (int j = 0; j < 4; ++j) { a0[j] = 0ull; a1[j] = 0ull; }

            const float* wp0 = p.w1_l2_W + (2 * vp) * EDIM + e;       // stride 544 over c
            const float* wp1 = wp0 + EDIM;
            float q0 = wp0[0 * 544], q1 = wp0[1 * 544], q2 = wp0[2 * 544], q3 = wp0[3 * 544];
            float s0 = wp1[0 * 544], s1 = wp1[1 * 544], s2 = wp1[2 * 544], s3 = wp1[3 * 544];
#pragma unroll 1
            for (int c = 0; c < HDIM; c += 4) {
                const int cn = (c + 4 < HDIM) ? c + 4 : 0;
                const float m0 = wp0[(cn + 0) * 544], m1 = wp0[(cn + 1) * 544];
                const float m2 = wp0[(cn + 2) * 544], m3 = wp0[(cn + 3) * 544];
                const float u0 = wp1[(cn + 0) * 544], u1 = wp1[(cn + 1) * 544];
                const float u2 = wp1[(cn + 2) * 544], u3 = wp1[(cn + 3) * 544];

                const ull w01_0 = pack2(q0, q1), w23_0 = pack2(q2, q3);
                const ull w01_1 = pack2(s0, s1), w23_1 = pack2(s2, s3);
#pragma unroll
                for (int j = 0; j < 4; ++j) {
                    const ulonglong2 h =
                        *reinterpret_cast<const ulonglong2*>(sH + (tg * 4 + j) * HDIM + c);
                    ull x0 = a0[j], x1 = a1[j];
                    x0 = fma2(h.x, w01_0, x0);
                    x1 = fma2(h.x, w01_1, x1);
                    x0 = fma2(h.y, w23_0, x0);
                    x1 = fma2(h.y, w23_1, x1);
                    a0[j] = x0; a1[j] = x1;
                }
                q0 = m0; q1 = m1; q2 = m2; q3 = m3;
                s0 = u0; s1 = u1; s2 = u2; s3 = u3;
            }
            const float bias0 = p.w1_l2_b[(2 * vp) * EDIM + e];
            const float bias1 = p.w1_l2_b[(2 * vp + 1) * EDIM + e];
#pragma unroll
            for (int j = 0; j < 4; ++j) {
                const float wv0 = fabsf(hsum2(a0[j]) + bias0);
                const float wv1 = fabsf(hsum2(a1[j]) + bias1);
                const int t = tg * 4 + j;
                float hh = hid[j];
                hh = fmaf(sGQ[t * 17 + 2 * vp],     wv0, hh);
                hh = fmaf(sGQ[t * 17 + 2 * vp + 1], wv1, hh);
                hid[j] = hh;
            }
        }
        // v = 16 (single trailing column)
        {
            ull a0[4];
#pragma unroll
            for (int j = 0; j < 4; ++j) a0[j] = 0ull;
            const float* wp = p.w1_l2_W + 16 * EDIM + e;
            float q0 = wp[0 * 544], q1 = wp[1 * 544], q2 = wp[2 * 544], q3 = wp[3 * 544];
#pragma unroll 1
            for (int c = 0; c < HDIM; c += 4) {
                const int cn = (c + 4 < HDIM) ? c + 4 : 0;
                const float m0 = wp[(cn + 0) * 544], m1 = wp[(cn + 1) * 544];
                const float m2 = wp[(cn + 2) * 544], m3 = wp[(cn + 3) * 544];
                const ull w01 = pack2(q0, q1), w23 = pack2(q2, q3);
#pragma unroll
                for (int j = 0; j < 4; ++j) {
                    const ulonglong2 h =
                        *reinterpret_cast<const ulonglong2*>(sH + (tg * 4 + j) * HDIM + c);
                    ull x = a0[j];
                    x = fma2(h.x, w01, x);
                    x = fma2(h.y, w23, x);
                    a0[j] = x;
                }
                q0 = m0; q1 = m1; q2 = m2; q3 = m3;
            }
            const float bias = p.w1_l2_b[16 * EDIM + e];
#pragma unroll
            for (int j = 0; j < 4; ++j) {
                const float wv = fabsf(hsum2(a0[j]) + bias);
                hid[j] = fmaf(sGQ[(tg * 4 + j) * 17 + 16], wv, hid[j]);
            }
        }
#pragma unroll
        for (int j = 0; j < 4; ++j) {
            const float x = hid[j];
            sHID[(tg * 4 + j) * EDIM + e] = (x > 0.f) ? x : expm1f(x);
        }
    }
    __syncthreads();

    // ---------------- P5: C1 (w2_l1, relu) + b2 chain smalls ----------------
    {
        gemm_colpair<HDIM, true>(sS, p.w2_l1_W, gc0,
                                 p.w2_l1_b[gc0], p.w2_l1_b[gc0 + 1], gt0, sH);
        // b2: relu(states @ b2_l1 + b) * b2_l2_W[e]  (pre-multiplied, summed in P7)
#pragma unroll 1
        for (int r = 0; r < 4; ++r) {
            const int i = tid + r * NT;       // 2048 items
            const int t = i >> 5;
            const int e = i & 31;
            const float v = fmaxf(dot512_2(sS + t * SDIM, p.b2_l1_W, EDIM, e) + p.b2_l1_b[e], 0.f);
            sHB2[t * EDIM + e] = v * p.b2_l2_W[e];
        }
    }
    __syncthreads();

    // ---------------- P6: w2 (256x32) + hidden*w2 products ----------------
    {
        const int e  = tid & 31;
        const int tg = tid >> 5;
        ull acc[4];
#pragma unroll
        for (int j = 0; j < 4; ++j) acc[j] = 0ull;

        const float* wp = p.w2_l2_W + e;
        ull w01 = pack2(wp[0 * EDIM], wp[1 * EDIM]);
        ull w23 = pack2(wp[2 * EDIM], wp[3 * EDIM]);
#pragma unroll 1
        for (int c = 0; c < HDIM; c += 4) {
            const int cn = (c + 4 < HDIM) ? c + 4 : 0;
            const float n0 = wp[(cn + 0) * EDIM];
            const float n1 = wp[(cn + 1) * EDIM];
            const float n2 = wp[(cn + 2) * EDIM];
            const float n3 = wp[(cn + 3) * EDIM];
#pragma unroll
            for (int j = 0; j < 4; ++j) {
                const ulonglong2 h =
                    *reinterpret_cast<const ulonglong2*>(sH + (tg * 4 + j) * HDIM + c);
                ull a = acc[j];
                a = fma2(h.x, w01, a);
                a = fma2(h.y, w23, a);
                acc[j] = a;
            }
            w01 = pack2(n0, n1);
            w23 = pack2(n2, n3);
        }
        const float bias = p.w2_l2_b[e];
#pragma unroll
        for (int j = 0; j < 4; ++j) {
            const int t = tg * 4 + j;
            const float w2v = fabsf(hsum2(acc[j]) + bias);
            sRED[t * EDIM + e] = sHID[t * EDIM + e] * w2v;
        }
    }
    __syncthreads();

    // ---------------- P7: final reduction ----------------
    if (tid < T_TOK) {
        const int t = tid;
        float s1 = 0.f, s2 = 0.f;
#pragma unroll
        for (int e = 0; e < EDIM; ++e) {
            s1 += sRED[t * EDIM + e];
            s2 += sHB2[t * EDIM + e];
        }
        p.out[(size_t)b * T_TOK + t] = s1 + s2 + p.b2_l2_b[0];
    }
}

extern "C" void kernel_launch(void* const* d_in, const int* in_sizes, int n_in,
                              void* d_out, int out_size)
{
    Params p;
    p.qvals    = (const float*)d_in[0];
    p.cr       = (const int*)  d_in[1];
    p.states   = (const float*)d_in[2];
    p.w00_l1_W = (const float*)d_in[3];
    p.w00_l1_b = (const float*)d_in[4];
    p.w00_l2_W = (const float*)d_in[5];
    p.w00_l2_b = (const float*)d_in[6];
    p.b00_W    = (const float*)d_in[7];
    p.b00_b    = (const float*)d_in[8];
    p.w01_W    = (const float*)d_in[9];
    p.w01_b    = (const float*)d_in[10];
    p.b01_W    = (const float*)d_in[11];
    p.b01_b    = (const float*)d_in[12];
    p.w1_l1_W  = (const float*)d_in[13];
    p.w1_l1_b  = (const float*)d_in[14];
    p.w1_l2_W  = (const float*)d_in[15];
    p.w1_l2_b  = (const float*)d_in[16];
    p.b1_W     = (const float*)d_in[17];
    p.b1_b     = (const float*)d_in[18];
    p.w2_l1_W  = (const float*)d_in[19];
    p.w2_l1_b  = (const float*)d_in[20];
    p.w2_l2_W  = (const float*)d_in[21];
    p.w2_l2_b  = (const float*)d_in[22];
    p.b2_l1_W  = (const float*)d_in[23];
    p.b2_l1_b  = (const float*)d_in[24];
    p.b2_l2_W  = (const float*)d_in[25];
    p.b2_l2_b  = (const float*)d_in[26];
    p.out      = (float*)d_out;

    const int Bn = in_sizes[2] / (T_TOK * SDIM);   // = 128

    cudaFuncSetAttribute(causal_mixer_kernel,
                         cudaFuncAttributeMaxDynamicSharedMemorySize, SMEM_BYTES);
    causal_mixer_kernel<<<Bn, NT, SMEM_BYTES>>>(p);
}

// round 10
// speedup vs baseline: 1.7610x; 1.1692x over previous
#include <cuda_runtime.h>
#include <math.h>

// Problem constants (fixed by the dataset)
//  B=128, T=64, NA=10, NV=16, K=4, SD=512, H=256, E=32
#define T_TOK   64
#define N_AG    10
#define N_VAR   16
#define K_REL   4
#define SDIM    512
#define HDIM    256
#define EDIM    32
#define NT      512

// shared memory layout (in floats)
#define SMEM_FLOATS 56528
#define SMEM_BYTES  (SMEM_FLOATS * 4)

typedef unsigned long long ull;

__device__ __forceinline__ ull fma2(ull a, ull b, ull c) {
    ull d;
    asm("fma.rn.f32x2 %0, %1, %2, %3;" : "=l"(d) : "l"(a), "l"(b), "l"(c));
    return d;
}
__device__ __forceinline__ ull pack2(float lo, float hi) {
    ull r;
    asm("mov.b64 %0, {%1, %2};" : "=l"(r) : "f"(lo), "f"(hi));
    return r;
}
__device__ __forceinline__ float hsum2(ull v) {
    float a, b;
    asm("mov.b64 {%0, %1}, %2;" : "=f"(a), "=f"(b) : "l"(v));
    return a + b;
}

struct Params {
    const float* qvals;      // (128,64,10)
    const int*   cr;         // (128,64,4,16)
    const float* states;     // (128,64,512)
    const float* w00_l1_W;   // (528,256)
    const float* w00_l1_b;   // (256)
    const float* w00_l2_W;   // (256,4)
    const float* w00_l2_b;   // (4)
    const float* b00_W;      // (528,1)
    const float* b00_b;      // (1)
    const float* w01_W;      // (512,10)
    const float* w01_b;      // (10)
    const float* b01_W;      // (512,1)
    const float* b01_b;      // (1)
    const float* w1_l1_W;    // (512,256)
    const float* w1_l1_b;    // (256)
    const float* w1_l2_W;    // (256,544)
    const float* w1_l2_b;    // (544)
    const float* b1_W;       // (512,32)
    const float* b1_b;       // (32)
    const float* w2_l1_W;    // (512,256)
    const float* w2_l1_b;    // (256)
    const float* w2_l2_W;    // (256,32)
    const float* w2_l2_b;    // (32)
    const float* b2_l1_W;    // (512,32)
    const float* b2_l1_b;    // (32)
    const float* b2_l2_W;    // (32,1)
    const float* b2_l2_b;    // (1)
    float*       out;        // (128,64,1)
};

// Stage-1 GEMM, column-QUAD version: one thread owns columns c0..c0+3 and
// 8 tokens. One LDS.128 of states feeds EIGHT FFMA2 (two per column);
// weight rows load as one coalesced float4.
template<int NC, bool RELU>
__device__ __forceinline__ void gemm_colquad(const float* __restrict__ sS,
                                             const float* __restrict__ W,
                                             const float* __restrict__ Wb,
                                             int c0, int t0,
                                             float* __restrict__ out)
{
    ull acc[4][8];
#pragma unroll
    for (int c = 0; c < 4; ++c)
#pragma unroll
        for (int t = 0; t < 8; ++t) acc[c][t] = 0ull;

    const float* wp = W + c0;        // c0 multiple of 4; float4 covers 4 cols
    float4 r0 = *reinterpret_cast<const float4*>(wp + 0 * NC);
    float4 r1 = *reinterpret_cast<const float4*>(wp + 1 * NC);
    float4 r2 = *reinterpret_cast<const float4*>(wp + 2 * NC);
    float4 r3 = *reinterpret_cast<const float4*>(wp + 3 * NC);
#pragma unroll 1
    for (int k = 0; k < SDIM; k += 4) {
        const int kn = (k + 4 < SDIM) ? (k + 4) : 0;   // last prefetch dummy, safe
        const float4 n0 = *reinterpret_cast<const float4*>(wp + (kn + 0) * NC);
        const float4 n1 = *reinterpret_cast<const float4*>(wp + (kn + 1) * NC);
        const float4 n2 = *reinterpret_cast<const float4*>(wp + (kn + 2) * NC);
        const float4 n3 = *reinterpret_cast<const float4*>(wp + (kn + 3) * NC);

        ull wA[4], wB[4];
        wA[0] = pack2(r0.x, r1.x); wA[1] = pack2(r0.y, r1.y);
        wA[2] = pack2(r0.z, r1.z); wA[3] = pack2(r0.w, r1.w);
        wB[0] = pack2(r2.x, r3.x); wB[1] = pack2(r2.y, r3.y);
        wB[2] = pack2(r2.z, r3.z); wB[3] = pack2(r2.w, r3.w);
#pragma unroll
        for (int t = 0; t < 8; ++t) {
            const ulonglong2 sv =
                *reinterpret_cast<const ulonglong2*>(sS + (t0 + t) * SDIM + k);
#pragma unroll
            for (int c = 0; c < 4; ++c) {
                ull x = acc[c][t];
                x = fma2(sv.x, wA[c], x);
                x = fma2(sv.y, wB[c], x);
                acc[c][t] = x;
            }
        }
        r0 = n0; r1 = n1; r2 = n2; r3 = n3;
    }
    const float4 bias = *reinterpret_cast<const float4*>(Wb + c0);
#pragma unroll
    for (int t = 0; t < 8; ++t) {
        float v0 = hsum2(acc[0][t]) + bias.x;
        float v1 = hsum2(acc[1][t]) + bias.y;
        float v2 = hsum2(acc[2][t]) + bias.z;
        float v3 = hsum2(acc[3][t]) + bias.w;
        if (RELU) {
            v0 = fmaxf(v0, 0.f); v1 = fmaxf(v1, 0.f);
            v2 = fmaxf(v2, 0.f); v3 = fmaxf(v3, 0.f);
        }
        *reinterpret_cast<float4*>(out + (t0 + t) * NC + c0) =
            make_float4(v0, v1, v2, v3);
    }
}

// Quad-column dot: one token's state vs 4 adjacent columns (e0..e0+3) of a
// row-major [512][32] matrix. 1 LDS + 4 coalesced LDG.128 per 8 FFMA2.
__device__ __forceinline__ float4 dot512_q32(const float* __restrict__ sSt,
                                             const float* __restrict__ W,
                                             int e0)
{
    ull a0 = 0ull, a1 = 0ull, a2 = 0ull, a3 = 0ull;
#pragma unroll 2
    for (int k = 0; k < SDIM; k += 4) {
        const ulonglong2 sv = *reinterpret_cast<const ulonglong2*>(sSt + k);
        const float4 w0 = *reinterpret_cast<const float4*>(W + (k + 0) * 32 + e0);
        const float4 w1 = *reinterpret_cast<const float4*>(W + (k + 1) * 32 + e0);
        const float4 w2 = *reinterpret_cast<const float4*>(W + (k + 2) * 32 + e0);
        const float4 w3 = *reinterpret_cast<const float4*>(W + (k + 3) * 32 + e0);
        a0 = fma2(sv.x, pack2(w0.x, w1.x), a0);
        a1 = fma2(sv.x, pack2(w0.y, w1.y), a1);
        a2 = fma2(sv.x, pack2(w0.z, w1.z), a2);
        a3 = fma2(sv.x, pack2(w0.w, w1.w), a3);
        a0 = fma2(sv.y, pack2(w2.x, w3.x), a0);
        a1 = fma2(sv.y, pack2(w2.y, w3.y), a1);
        a2 = fma2(sv.y, pack2(w2.z, w3.z), a2);
        a3 = fma2(sv.y, pack2(w2.w, w3.w), a3);
    }
    return make_float4(hsum2(a0), hsum2(a1), hsum2(a2), hsum2(a3));
}

// f32x2 dot of one state row vs column c of row-major [512][NC]
__device__ __forceinline__ float dot512_2(const float* __restrict__ sSt,
                                          const float* __restrict__ W,
                                          int NC, int c)
{
    ull acc = 0ull;
#pragma unroll 4
    for (int k = 0; k < SDIM; k += 4) {
        const ulonglong2 sv = *reinterpret_cast<const ulonglong2*>(sSt + k);
        const ull w01 = pack2(W[(k + 0) * NC + c], W[(k + 1) * NC + c]);
        const ull w23 = pack2(W[(k + 2) * NC + c], W[(k + 3) * NC + c]);
        acc = fma2(sv.x, w01, acc);
        acc = fma2(sv.y, w23, acc);
    }
    return hsum2(acc);
}

extern __shared__ float smem[];

__global__ void __launch_bounds__(NT, 1)
causal_mixer_kernel(Params p)
{
    const int tid = threadIdx.x;
    const int b   = blockIdx.x;          // one block == one batch index (64 tokens)

    float* sS    = smem;                 // [64][512]  32768
    float* sH    = smem + 32768;         // [64][256]  16384
    float* sU1   = smem + 49152;         // 2048 union
    float* sQ    = sU1;                  // [64][10]
    float* sW01  = sU1 + 640;            // [64][10]
    float* sHd   = sU1 + 1280;           // [256]
    float* sW0   = sU1 + 1536;           // [64][4]
    float* sW0v  = sU1 + 1792;           // [64][4]
    float* sHB2  = sU1;                  // alias [64][32] (valid from P5)
    float* sGQ   = smem + 51200;         // [64][17]
    float* sHID  = smem + 52288;         // [64][32]
    float* sB1   = smem + 54336;         // [64][32]
    float* sRED  = sB1;                  // alias (valid from P6)
    float* sGB   = smem + 56384;         // [64]
    float* sB01  = smem + 56448;         // [64]
    float* sMisc = smem + 56512;         // [0] = g_delta

    // per-thread gemm coordinates: 64 column-quads x 8 token-groups of 8
    const int gc0 = (tid & 63) * 4;
    const int gt0 = (tid >> 6) * 8;
    // per-thread small-dot coordinates: token + 4 adjacent columns
    const int qt  = tid >> 3;
    const int qe0 = (tid & 7) * 4;

    // ---------------- P0: load states + qvals, h_delta / g_delta ----------------
    {
        const float4* src = reinterpret_cast<const float4*>(p.states + (size_t)b * T_TOK * SDIM);
        float4* dst = reinterpret_cast<float4*>(sS);
#pragma unroll
        for (int i = tid; i < T_TOK * SDIM / 4; i += NT) dst[i] = src[i];

        const float* qsrc = p.qvals + (size_t)b * T_TOK * N_AG;
#pragma unroll
        for (int i = tid; i < T_TOK * N_AG; i += NT) sQ[i] = qsrc[i];

        if (tid < HDIM) {
            // h_delta[c] = sum of one-hot rows (512..527) of w00_l1_W
            float hd = 0.f;
#pragma unroll
            for (int r = 0; r < N_VAR; ++r) hd += p.w00_l1_W[(SDIM + r) * HDIM + tid];
            sHd[tid] = hd;
        }
        if (tid == 0) {
            float gd = 0.f;
#pragma unroll
            for (int r = 0; r < N_VAR; ++r) gd += p.b00_W[SDIM + r];
            sMisc[0] = gd;
        }
    }
    __syncthreads();

    // ---------------- P1: small stage-1 columns + A1 (w00_l1 pre-activation) ----------------
    {
        // b1: 64 tokens x 32 cols as quad-dots (one thread: 1 token, 4 cols)
        {
            const float4 v = dot512_q32(sS + qt * SDIM, p.b1_W, qe0);
            const float4 bb = *reinterpret_cast<const float4*>(p.b1_b + qe0);
            *reinterpret_cast<float4*>(sB1 + qt * EDIM + qe0) =
                make_float4(v.x + bb.x, v.y + bb.y, v.z + bb.z, v.w + bb.w);
        }
        // misc 12 columns x 64 tokens = 768 items, 2 guarded rounds
#pragma unroll 1
        for (int r = 0; r < 2; ++r) {
            const int i = tid + r * NT;
            if (i < 768) {
                const int t = i / 12;
                const int j = i % 12;
                const float* sSt = sS + t * SDIM;
                if (j == 0)      sGB[t]  = dot512_2(sSt, p.b00_W, 1, 0) + p.b00_b[0];
                else if (j == 1) sB01[t] = dot512_2(sSt, p.b01_W, 1, 0) + p.b01_b[0];
                else {
                    const int c = j - 2;
                    sW01[t * N_AG + c] = dot512_2(sSt, p.w01_W, N_AG, c) + p.w01_b[c];
                }
            }
        }
        // A1: h00 pre-activation (relu deferred; delta-variant needs pre-act)
        gemm_colquad<HDIM, false>(sS, p.w00_l1_W, p.w00_l1_b, gc0, gt0, sH);
    }
    __syncthreads();

    // ---------------- P2: A2 — per-token w0 (base + onehot variant split over threads) ----------------
    {
        // 512 items = 64 tokens x 4 k x {base, variant}
        const int t    = tid >> 3;
        const int k4   = (tid >> 1) & 3;
        const int var  = tid & 1;
        float a = 0.f;
#pragma unroll 4
        for (int c = 0; c < HDIM; c += 4) {
            const float4 h4 = *reinterpret_cast<const float4*>(sH + t * HDIM + c);
            float h0 = h4.x, h1 = h4.y, h2 = h4.z, h3 = h4.w;
            if (var) { h0 += sHd[c]; h1 += sHd[c + 1]; h2 += sHd[c + 2]; h3 += sHd[c + 3]; }
            a = fmaf(fmaxf(h0, 0.f), p.w00_l2_W[(c + 0) * K_REL + k4], a);
            a = fmaf(fmaxf(h1, 0.f), p.w00_l2_W[(c + 1) * K_REL + k4], a);
            a = fmaf(fmaxf(h2, 0.f), p.w00_l2_W[(c + 2) * K_REL + k4], a);
            a = fmaf(fmaxf(h3, 0.f), p.w00_l2_W[(c + 3) * K_REL + k4], a);
        }
        a += p.w00_l2_b[k4];
        if (var) sW0v[t * K_REL + k4] = a;
        else     sW0 [t * K_REL + k4] = a;
    }
    __syncthreads();

    // ---------------- P3: group + other -> gq ; then B1 (w1_l1, relu) ----------------
    {
        const float gdelta = sMisc[0];
#pragma unroll 1
        for (int r = 0; r < 2; ++r) {
            const int i = tid + r * NT;       // 1024 items = 64 tokens x 16 vars
            const int t = i >> 4;
            const int v = i & 15;
            const bool var = (v == b);
            const float* w0p = var ? (sW0v + t * K_REL) : (sW0 + t * K_REL);
            float g = sGB[t] + (var ? gdelta : 0.f);
            const int* crp = p.cr + (((size_t)b * T_TOK + t) * K_REL) * N_VAR + v;
#pragma unroll
            for (int k = 0; k < K_REL; ++k) {
                const int a = crp[k * N_VAR];
                g = fmaf(sQ[t * N_AG + a], fabsf(w0p[k]), g);
            }
            sGQ[t * 17 + v] = g;
        }
        if (tid < T_TOK) {
            const int t = tid;
            float o = sB01[t];
#pragma unroll
            for (int a = 0; a < N_AG; ++a)
                o = fmaf(sQ[t * N_AG + a], sW01[t * N_AG + a], o);
            sGQ[t * 17 + 16] = o;
        }
        // B1: h1 = relu(states @ w1_l1 + b) into sH
        gemm_colquad<HDIM, true>(sS, p.w1_l1_W, p.w1_l1_b, gc0, gt0, sH);
    }
    __syncthreads();

    // ---------------- P4: big stage-2 — w1 (256x544) fused with gq-mix + b1 + elu ----------------
    // v-columns processed in QUADS: one LDS.128 of hidden feeds 8 FFMA2.
    {
        const int e  = tid & 31;
        const int tg = tid >> 5;       // 16 groups, each owns tokens tg*4 .. tg*4+3
        float hid[4];
#pragma unroll
        for (int j = 0; j < 4; ++j) hid[j] = sB1[(tg * 4 + j) * EDIM + e];

#pragma unroll 1
        for (int vq = 0; vq < 4; ++vq) {
            ull a[4][4];               // [vi][token]
#pragma unroll
            for (int vi = 0; vi < 4; ++vi)
#pragma unroll
                for (int j = 0; j < 4; ++j) a[vi][j] = 0ull;

            const float* wp = p.w1_l2_W + (4 * vq) * EDIM + e;   // +vi*32, stride 544 over c
            float cw[4][4];            // [vi][row]
#pragma unroll
            for (int vi = 0; vi < 4; ++vi)
#pragma unroll
                for (int rr = 0; rr < 4; ++rr) cw[vi][rr] = wp[rr * 544 + vi * EDIM];

#pragma unroll 1
            for (int c = 0; c < HDIM; c += 4) {
                const int cn = (c + 4 < HDIM) ? c + 4 : 0;
                float nw[4][4];
#pragma unroll
                for (int vi = 0; vi < 4; ++vi)
#pragma unroll
                    for (int rr = 0; rr < 4; ++rr)
                        nw[vi][rr] = wp[(cn + rr) * 544 + vi * EDIM];

                ull wA[4], wB[4];
#pragma unroll
                for (int vi = 0; vi < 4; ++vi) {
                    wA[vi] = pack2(cw[vi][0], cw[vi][1]);
                    wB[vi] = pack2(cw[vi][2], cw[vi][3]);
                }
#pragma unroll
                for (int j = 0; j < 4; ++j) {
                    const ulonglong2 h =
                        *reinterpret_cast<const ulonglong2*>(sH + (tg * 4 + j) * HDIM + c);
#pragma unroll
                    for (int vi = 0; vi < 4; ++vi) {
                        ull x = a[vi][j];
                        x = fma2(h.x, wA[vi], x);
                        x = fma2(h.y, wB[vi], x);
                        a[vi][j] = x;
                    }
                }
#pragma unroll
                for (int vi = 0; vi < 4; ++vi)
#pragma unroll
                    for (int rr = 0; rr < 4; ++rr) cw[vi][rr] = nw[vi][rr];
            }
#pragma unroll
            for (int vi = 0; vi < 4; ++vi) {
                const int v = 4 * vq + vi;
                const float bias = p.w1_l2_b[v * EDIM + e];
#pragma unroll
                for (int j = 0; j < 4; ++j) {
                    const float wv = fabsf(hsum2(a[vi][j]) + bias);
                    hid[j] = fmaf(sGQ[(tg * 4 + j) * 17 + v], wv, hid[j]);
                }
            }
        }
        // v = 16 (single trailing column)
        {
            ull a0[4];
#pragma unroll
            for (int j = 0; j < 4; ++j) a0[j] = 0ull;
            const float* wp = p.w1_l2_W + 16 * EDIM + e;
            float q0 = wp[0 * 544], q1 = wp[1 * 544], q2 = wp[2 * 544], q3 = wp[3 * 544];
#pragma unroll 1
            for (int c = 0; c < HDIM; c += 4) {
                const int cn = (c + 4 < HDIM) ? c + 4 : 0;
                const float m0 = wp[(cn + 0) * 544], m1 = wp[(cn + 1) * 544];
                const float m2 = wp[(cn + 2) * 544], m3 = wp[(cn + 3) * 544];
                const ull w01 = pack2(q0, q1), w23 = pack2(q2, q3);
#pragma unroll
                for (int j = 0; j < 4; ++j) {
                    const ulonglong2 h =
                        *reinterpret_cast<const ulonglong2*>(sH + (tg * 4 + j) * HDIM + c);
                    ull x = a0[j];
                    x = fma2(h.x, w01, x);
                    x = fma2(h.y, w23, x);
                    a0[j] = x;
                }
                q0 = m0; q1 = m1; q2 = m2; q3 = m3;
            }
            const float bias = p.w1_l2_b[16 * EDIM + e];
#pragma unroll
            for (int j = 0; j < 4; ++j) {
                const float wv = fabsf(hsum2(a0[j]) + bias);
                hid[j] = fmaf(sGQ[(tg * 4 + j) * 17 + 16], wv, hid[j]);
            }
        }
#pragma unroll
        for (int j = 0; j < 4; ++j) {
            const float x = hid[j];
            sHID[(tg * 4 + j) * EDIM + e] = (x > 0.f) ? x : expm1f(x);
        }
    }
    __syncthreads();

    // ---------------- P5: C1 (w2_l1, relu) + b2 chain smalls ----------------
    {
        gemm_colquad<HDIM, true>(sS, p.w2_l1_W, p.w2_l1_b, gc0, gt0, sH);
        // b2: relu(states @ b2_l1 + b) * b2_l2_W[e]  (pre-multiplied, summed in P7)
        {
            const float4 v  = dot512_q32(sS + qt * SDIM, p.b2_l1_W, qe0);
            const float4 bb = *reinterpret_cast<const float4*>(p.b2_l1_b + qe0);
            const float4 ww = *reinterpret_cast<const float4*>(p.b2_l2_W + qe0);
            *reinterpret_cast<float4*>(sHB2 + qt * EDIM + qe0) = make_float4(
                fmaxf(v.x + bb.x, 0.f) * ww.x,
                fmaxf(v.y + bb.y, 0.f) * ww.y,
                fmaxf(v.z + bb.z, 0.f) * ww.z,
                fmaxf(v.w + bb.w, 0.f) * ww.w);
        }
    }
    __syncthreads();

    // ---------------- P6: w2 (256x32) + hidden*w2 products ----------------
    {
        const int e  = tid & 31;
        const int tg = tid >> 5;
        ull acc[4];
#pragma unroll
        for (int j = 0; j < 4; ++j) acc[j] = 0ull;

        const float* wp = p.w2_l2_W + e;
        ull w01 = pack2(wp[0 * EDIM], wp[1 * EDIM]);
        ull w23 = pack2(wp[2 * EDIM], wp[3 * EDIM]);
#pragma unroll 1
        for (int c = 0; c < HDIM; c += 4) {
            const int cn = (c + 4 < HDIM) ? c + 4 : 0;
            const float n0 = wp[(cn + 0) * EDIM];
            const float n1 = wp[(cn + 1) * EDIM];
            const float n2 = wp[(cn + 2) * EDIM];
            const float n3 = wp[(cn + 3) * EDIM];
#pragma unroll
            for (int j = 0; j < 4; ++j) {
                const ulonglong2 h =
                    *reinterpret_cast<const ulonglong2*>(sH + (tg * 4 + j) * HDIM + c);
                ull a = acc[j];
                a = fma2(h.x, w01, a);
                a = fma2(h.y, w23, a);
                acc[j] = a;
            }
            w01 = pack2(n0, n1);
            w23 = pack2(n2, n3);
        }
        const float bias = p.w2_l2_b[e];
#pragma unroll
        for (int j = 0; j < 4; ++j) {
            const int t = tg * 4 + j;
            const float w2v = fabsf(hsum2(acc[j]) + bias);
            sRED[t * EDIM + e] = sHID[t * EDIM + e] * w2v;
        }
    }
    __syncthreads();

    // ---------------- P7: final reduction ----------------
    if (tid < T_TOK) {
        const int t = tid;
        float s1 = 0.f, s2 = 0.f;
#pragma unroll
        for (int e = 0; e < EDIM; ++e) {
            s1 += sRED[t * EDIM + e];
            s2 += sHB2[t * EDIM + e];
        }
        p.out[(size_t)b * T_TOK + t] = s1 + s2 + p.b2_l2_b[0];
    }
}

extern "C" void kernel_launch(void* const* d_in, const int* in_sizes, int n_in,
                              void* d_out, int out_size)
{
    Params p;
    p.qvals    = (const float*)d_in[0];
    p.cr       = (const int*)  d_in[1];
    p.states   = (const float*)d_in[2];
    p.w00_l1_W = (const float*)d_in[3];
    p.w00_l1_b = (const float*)d_in[4];
    p.w00_l2_W = (const float*)d_in[5];
    p.w00_l2_b = (const float*)d_in[6];
    p.b00_W    = (const float*)d_in[7];
    p.b00_b    = (const float*)d_in[8];
    p.w01_W    = (const float*)d_in[9];
    p.w01_b    = (const float*)d_in[10];
    p.b01_W    = (const float*)d_in[11];
    p.b01_b    = (const float*)d_in[12];
    p.w1_l1_W  = (const float*)d_in[13];
    p.w1_l1_b  = (const float*)d_in[14];
    p.w1_l2_W  = (const float*)d_in[15];
    p.w1_l2_b  = (const float*)d_in[16];
    p.b1_W     = (const float*)d_in[17];
    p.b1_b     = (const float*)d_in[18];
    p.w2_l1_W  = (const float*)d_in[19];
    p.w2_l1_b  = (const float*)d_in[20];
    p.w2_l2_W  = (const float*)d_in[21];
    p.w2_l2_b  = (const float*)d_in[22];
    p.b2_l1_W  = (const float*)d_in[23];
    p.b2_l1_b  = (const float*)d_in[24];
    p.b2_l2_W  = (const float*)d_in[25];
    p.b2_l2_b  = (const float*)d_in[26];
    p.out      = (float*)d_out;

    const int Bn = in_sizes[2] / (T_TOK * SDIM);   // = 128

    cudaFuncSetAttribute(causal_mixer_kernel,
                         cudaFuncAttributeMaxDynamicSharedMemorySize, SMEM_BYTES);
    causal_mixer_kernel<<<Bn, NT, SMEM_BYTES>>>(p);
}